// round 15
// baseline (speedup 1.0000x reference)
#include <cuda_runtime.h>
#include <math.h>

// Problem constants
#define Sv   512
#define Bv   64
#define FINv 512
#define Hv   512
#define G4   2048   // 4*H

__device__ float g_gx[(size_t)Sv * Bv * G4];

// h(t-1) in pre-split packed-bf16 form, FRAGMENT-PERMUTED layout:
// word index (r, j) -> r*256 + (j&3)*64 + (j>>2), j = k>>1 (bf16 pair).
// Written by producers each step; read as 4x LDG.128 per thread per array.
__device__ __align__(16) unsigned g_hhi_w[Bv * 256];
__device__ __align__(16) unsigned g_hlo_w[Bv * 256];

// Grid-barrier state (R13 counter/gen form — measured best).
__device__ unsigned int g_count = 0;
__device__ unsigned int g_gen   = 0;

#define NBLK 128

__device__ __forceinline__ unsigned cvt_tf32(float x) {
    unsigned u;
    asm("cvt.rna.tf32.f32 %0, %1;" : "=r"(u) : "f"(x));
    return u;
}

__device__ __forceinline__ void mma_tf32(float c[4], const unsigned a[4],
                                         const unsigned b[2]) {
    asm("mma.sync.aligned.m16n8k8.row.col.f32.tf32.tf32.f32 "
        "{%0,%1,%2,%3}, {%4,%5,%6,%7}, {%8,%9}, {%0,%1,%2,%3};"
        : "+f"(c[0]), "+f"(c[1]), "+f"(c[2]), "+f"(c[3])
        : "r"(a[0]), "r"(a[1]), "r"(a[2]), "r"(a[3]),
          "r"(b[0]), "r"(b[1]));
}

__device__ __forceinline__ void mma_bf16(float c[4], const unsigned a[4],
                                         const unsigned b[2]) {
    asm("mma.sync.aligned.m16n8k16.row.col.f32.bf16.bf16.f32 "
        "{%0,%1,%2,%3}, {%4,%5,%6,%7}, {%8,%9}, {%0,%1,%2,%3};"
        : "+f"(c[0]), "+f"(c[1]), "+f"(c[2]), "+f"(c[3])
        : "r"(a[0]), "r"(a[1]), "r"(a[2]), "r"(a[3]),
          "r"(b[0]), "r"(b[1]));
}

__device__ __forceinline__ void bf16_split2(float e0, float e1,
                                            unsigned& hi, unsigned& lo) {
    asm("cvt.rn.bf16x2.f32 %0, %1, %2;" : "=r"(hi) : "f"(e1), "f"(e0));
    float f0 = __uint_as_float(hi << 16);
    float f1 = __uint_as_float(hi & 0xffff0000u);
    float r0 = e0 - f0;
    float r1 = e1 - f1;
    asm("cvt.rn.bf16x2.f32 %0, %1, %2;" : "=r"(lo) : "f"(r1), "f"(r0));
}

__device__ __forceinline__ unsigned short bf16_of(float x) {
    unsigned short h;
    asm("cvt.rn.bf16.f32 %0, %1;" : "=h"(h) : "f"(x));
    return h;
}

// ===========================================================================
// Phase 1: gx = X[32768,512] @ W_ih^T[512,2048] + (b_ih + b_hh)
// tf32 mma.m16n8k8, 128x128 block tile, 8 warps, 64x32 warp tile. (R6, kept.)
// ===========================================================================
#define P1ROW 36

__global__ __launch_bounds__(256, 2) void gemm_x_tf32(
    const float* __restrict__ X,
    const float* __restrict__ W,
    const float* __restrict__ bih,
    const float* __restrict__ bhh)
{
    __shared__ unsigned As[128 * P1ROW];
    __shared__ unsigned Bs[128 * P1ROW];

    const int tid  = threadIdx.x;
    const int wid  = tid >> 5;
    const int lane = tid & 31;
    const int g    = lane >> 2;
    const int t    = lane & 3;

    const int m0 = blockIdx.y * 128;
    const int n0 = blockIdx.x * 128;
    const int wm = (wid >> 2) * 64;
    const int wn = (wid & 3) * 32;

    const int lr  = tid >> 3;
    const int lc4 = (tid & 7) * 4;

    float acc[4][4][4];
#pragma unroll
    for (int mi = 0; mi < 4; mi++)
#pragma unroll
        for (int nj = 0; nj < 4; nj++)
#pragma unroll
            for (int q = 0; q < 4; q++) acc[mi][nj][q] = 0.f;

    for (int k0 = 0; k0 < FINv; k0 += 32) {
#pragma unroll
        for (int rr = 0; rr < 128; rr += 32) {
            int row = lr + rr;
            float4 av = *reinterpret_cast<const float4*>(
                X + (size_t)(m0 + row) * FINv + k0 + lc4);
            uint4 at = make_uint4(cvt_tf32(av.x), cvt_tf32(av.y),
                                  cvt_tf32(av.z), cvt_tf32(av.w));
            *reinterpret_cast<uint4*>(&As[row * P1ROW + lc4]) = at;
            float4 bv = *reinterpret_cast<const float4*>(
                W + (size_t)(n0 + row) * FINv + k0 + lc4);
            uint4 bt = make_uint4(cvt_tf32(bv.x), cvt_tf32(bv.y),
                                  cvt_tf32(bv.z), cvt_tf32(bv.w));
            *reinterpret_cast<uint4*>(&Bs[row * P1ROW + lc4]) = bt;
        }
        __syncthreads();

#pragma unroll
        for (int kk = 0; kk < 32; kk += 8) {
            unsigned afr[4][4], bfr[4][2];
#pragma unroll
            for (int mi = 0; mi < 4; mi++) {
                int base = (wm + mi * 16 + g) * P1ROW + kk + t;
                afr[mi][0] = As[base];
                afr[mi][1] = As[base + 8 * P1ROW];
                afr[mi][2] = As[base + 4];
                afr[mi][3] = As[base + 8 * P1ROW + 4];
            }
#pragma unroll
            for (int nj = 0; nj < 4; nj++) {
                int bb = (wn + nj * 8 + g) * P1ROW + kk + t;
                bfr[nj][0] = Bs[bb];
                bfr[nj][1] = Bs[bb + 4];
            }
#pragma unroll
            for (int mi = 0; mi < 4; mi++)
#pragma unroll
                for (int nj = 0; nj < 4; nj++)
                    mma_tf32(acc[mi][nj], afr[mi], bfr[nj]);
        }
        __syncthreads();
    }

#pragma unroll
    for (int nj = 0; nj < 4; nj++) {
        int n = n0 + wn + nj * 8 + 2 * t;
        float bs0 = bih[n] + bhh[n];
        float bs1 = bih[n + 1] + bhh[n + 1];
#pragma unroll
        for (int mi = 0; mi < 4; mi++) {
            int row = m0 + wm + mi * 16 + g;
            float2 v0 = make_float2(acc[mi][nj][0] + bs0, acc[mi][nj][1] + bs1);
            float2 v1 = make_float2(acc[mi][nj][2] + bs0, acc[mi][nj][3] + bs1);
            *reinterpret_cast<float2*>(&g_gx[(size_t)row * G4 + n])       = v0;
            *reinterpret_cast<float2*>(&g_gx[(size_t)(row + 8) * G4 + n]) = v1;
        }
    }
}

// ===========================================================================
// Phase 2: persistent recurrence, bf16-pair tensor cores, 512 threads.
// NO smem h staging: A-fragments (h) load straight from the fragment-permuted
// global arrays (4x LDG.128 per thread per array per row), disjoint across
// warps. W (hi,lo) stays in smem; split-K=4 via 4-slab ex reduce; counter/gen
// grid barrier (R13); c in registers.
// ===========================================================================
#define HS 260
#define WHI_OFF 0
#define WLO_OFF (16 * HS)
#define EX_OFF  (32 * HS)                    // 8320
#define EXSLAB  (16 * 68)
#define SM2_WORDS (EX_OFF + 4 * EXSLAB)      // 12672 words = 50688 B

__global__ __launch_bounds__(512, 1) void lstm_rec_kernel(
    const float* __restrict__ whh,   // [2048][512]
    float* __restrict__ out)
{
    extern __shared__ unsigned smu[];
    unsigned* w_hi = smu + WHI_OFF;
    unsigned* w_lo = smu + WLO_OFF;
    float*    ex   = reinterpret_cast<float*>(smu + EX_OFF);  // [4][16][68]

    float* hs_out = out;
    float* cs_out = out + (size_t)Sv * Bv * Hv;

    const int tid  = threadIdx.x;
    const int wid  = tid >> 5;
    const int lane = tid & 31;
    const int g    = lane >> 2;
    const int t    = lane & 3;
    const int u0   = blockIdx.x * 4;
    const int kq   = wid >> 2;           // K quarter
    const int bb   = (wid & 3) * 16;     // batch base

    // W_hh split into packed bf16 (hi, lo) pair words, once.
    for (int i = tid; i < 16 * 256; i += 512) {
        int c = i >> 8, j = i & 255;
        int gr = ((c >> 2) * Hv) + u0 + (c & 3);
        float2 wv = *reinterpret_cast<const float2*>(whh + (size_t)gr * Hv + 2 * j);
        unsigned hi, lo;
        bf16_split2(wv.x, wv.y, hi, lo);
        w_hi[c * HS + j] = hi;
        w_lo[c * HS + j] = lo;
    }

    unsigned bar_base = 0;
    if (tid == 0) bar_base = atomicAdd(&g_gen, 0u);

    // A-fragment global bases (word indices; 64B-aligned)
    const int hb0 = (bb + g) * 256 + t * 64 + kq * 16;
    const int hb1 = (bb + g + 8) * 256 + t * 64 + kq * 16;
    // B-fragment smem bases
    const int b0 = g * HS + t;
    const int b1 = (8 + g) * HS + t;
    const int jh = kq * 64;

    // Accumulator cols: nt*8 + 2t, +1 (adjacent units of the same gate)
    int gcol[2];
#pragma unroll
    for (int nt = 0; nt < 2; nt++) {
        int c = nt * 8 + 2 * t;
        gcol[nt] = ((c >> 2) * Hv) + u0 + (c & 3);
    }

    // Elementwise mapping (threads tid<256): one (unit,batch); c in register.
    const int u_e = tid & 3;
    const int b_e = (tid >> 2) & 63;
    // Producer-side permuted h address (16-bit units)
    const int kg    = u0 + u_e;
    const int pj    = kg >> 1;
    const int saddr = (((b_e * 256) + (pj & 3) * 64 + (pj >> 2)) << 1) | (kg & 1);
    float cpv = 0.f;

    __syncthreads();

    for (int t_s = 0; t_s < Sv; t_s++) {
        // ---- prefetch gx into regs ----
        float gxv[2][4];
        if (kq == 0) {
            const float* gxt = g_gx + (size_t)t_s * (Bv * G4);
#pragma unroll
            for (int nt = 0; nt < 2; nt++) {
                float2 lo = *reinterpret_cast<const float2*>(
                    gxt + (size_t)(bb + g) * G4 + gcol[nt]);
                float2 hi = *reinterpret_cast<const float2*>(
                    gxt + (size_t)(bb + g + 8) * G4 + gcol[nt]);
                gxv[nt][0] = lo.x; gxv[nt][1] = lo.y;
                gxv[nt][2] = hi.x; gxv[nt][3] = hi.y;
            }
        } else {
#pragma unroll
            for (int nt = 0; nt < 2; nt++)
#pragma unroll
                for (int q = 0; q < 4; q++) gxv[nt][q] = 0.f;
        }

        float acc[2][4];
#pragma unroll
        for (int nt = 0; nt < 2; nt++)
#pragma unroll
            for (int q = 0; q < 4; q++) acc[nt][q] = gxv[nt][q];

        if (t_s > 0) {
            // ---- grid barrier: all blocks finished step t_s-1 ----
            __syncthreads();
            if (tid == 0) {
                unsigned target = bar_base + (unsigned)t_s;
                if (atomicAdd(&g_count, 1u) == NBLK - 1u) {
                    atomicExch(&g_count, 0u);
                    __threadfence();
                    atomicExch(&g_gen, target);
                } else {
                    while ((int)(atomicAdd(&g_gen, 0u) - target) < 0) { }
                }
                __threadfence();
            }
            __syncthreads();

            // ---- load A-fragments straight from permuted global h ----
            union { uint4 v[4]; unsigned u[8 * 2]; } r0h, r1h, r0l, r1l;
#pragma unroll
            for (int i = 0; i < 4; i++) {
                r0h.v[i] = __ldcg(reinterpret_cast<const uint4*>(g_hhi_w + hb0) + i);
                r1h.v[i] = __ldcg(reinterpret_cast<const uint4*>(g_hhi_w + hb1) + i);
                r0l.v[i] = __ldcg(reinterpret_cast<const uint4*>(g_hlo_w + hb0) + i);
                r1l.v[i] = __ldcg(reinterpret_cast<const uint4*>(g_hlo_w + hb1) + i);
            }

            // ---- bf16-pair recurrent GEMM: K quarter ----
#pragma unroll
            for (int kt = 0; kt < 8; kt++) {
                int jb = jh + kt * 8;
                unsigned ah[4], al[4], bh[2][2], bl[2][2];
                ah[0] = r0h.u[2 * kt];     ah[1] = r1h.u[2 * kt];
                ah[2] = r0h.u[2 * kt + 1]; ah[3] = r1h.u[2 * kt + 1];
                al[0] = r0l.u[2 * kt];     al[1] = r1l.u[2 * kt];
                al[2] = r0l.u[2 * kt + 1]; al[3] = r1l.u[2 * kt + 1];
                bh[0][0] = w_hi[b0 + jb];  bh[0][1] = w_hi[b0 + jb + 4];
                bh[1][0] = w_hi[b1 + jb];  bh[1][1] = w_hi[b1 + jb + 4];
                bl[0][0] = w_lo[b0 + jb];  bl[0][1] = w_lo[b0 + jb + 4];
                bl[1][0] = w_lo[b1 + jb];  bl[1][1] = w_lo[b1 + jb + 4];
#pragma unroll
                for (int nt = 0; nt < 2; nt++) {
                    mma_bf16(acc[nt], ah, bh[nt]);   // Whi*Hhi
                    mma_bf16(acc[nt], al, bh[nt]);   // Whi*Hlo
                    mma_bf16(acc[nt], ah, bl[nt]);   // Wlo*Hhi
                }
            }
        }

        // ---- write split-K partials to ex[kq] ----
        {
            float* exs = ex + kq * EXSLAB;
#pragma unroll
            for (int nt = 0; nt < 2; nt++) {
                int c = nt * 8 + 2 * t;
                exs[c * 68 + bb + g]           = acc[nt][0];
                exs[(c + 1) * 68 + bb + g]     = acc[nt][1];
                exs[c * 68 + bb + g + 8]       = acc[nt][2];
                exs[(c + 1) * 68 + bb + g + 8] = acc[nt][3];
            }
        }
        __syncthreads();

        // ---- fused 4-way reduce + LSTM update + permuted h pre-split ----
        if (tid < 256) {
            float gate[4];
#pragma unroll
            for (int gg4 = 0; gg4 < 4; gg4++) {
                int c = gg4 * 4 + u_e;
                float s = ex[c * 68 + b_e];
#pragma unroll
                for (int sk = 1; sk < 4; sk++)
                    s += ex[sk * EXSLAB + c * 68 + b_e];
                gate[gg4] = s;
            }
            float si = 1.f / (1.f + expf(-gate[0]));
            float sf = 1.f / (1.f + expf(-gate[1]));
            float tg = tanhf(gate[2]);
            float so = 1.f / (1.f + expf(-gate[3]));
            float cc = sf * cpv + si * tg;
            cpv = cc;
            float hh = so * tanhf(cc);
            // pre-split h for next step's consumers, permuted layout
            unsigned short hi16 = bf16_of(hh);
            float fhi = __uint_as_float(((unsigned)hi16) << 16);
            unsigned short lo16 = bf16_of(hh - fhi);
            reinterpret_cast<unsigned short*>(g_hhi_w)[saddr] = hi16;
            reinterpret_cast<unsigned short*>(g_hlo_w)[saddr] = lo16;
            // fp32 outputs
            size_t o = (size_t)t_s * Bv * Hv + (size_t)b_e * Hv + u0 + u_e;
            __stcg(hs_out + o, hh);
            __stcg(cs_out + o, cc);
            __threadfence();   // make h stores visible before the arrive
        }
        // (next iteration's barrier __syncthreads orders the arrive)
    }
}

// ===========================================================================
// Launch
// ===========================================================================
extern "C" void kernel_launch(void* const* d_in, const int* in_sizes, int n_in,
                              void* d_out, int out_size)
{
    const float* seq  = (const float*)d_in[0];
    const float* w_ih = (const float*)d_in[1];
    const float* w_hh = (const float*)d_in[2];
    const float* b_ih = (const float*)d_in[3];
    const float* b_hh = (const float*)d_in[4];
    float* out = (float*)d_out;

    const int smem_p2 = SM2_WORDS * (int)sizeof(unsigned);   // 50688 B
    cudaFuncSetAttribute(lstm_rec_kernel,
                         cudaFuncAttributeMaxDynamicSharedMemorySize, smem_p2);

    dim3 g1(G4 / 128, (Sv * Bv) / 128);   // (16, 256)
    gemm_x_tf32<<<g1, 256>>>(seq, w_ih, b_ih, b_hh);
    lstm_rec_kernel<<<NBLK, 512, smem_p2>>>(w_hh, out);
}

// round 16
// speedup vs baseline: 1.6310x; 1.6310x over previous
#include <cuda_runtime.h>
#include <math.h>

// Problem constants
#define Sv   512
#define Bv   64
#define FINv 512
#define Hv   512
#define G4   2048   // 4*H

__device__ float g_gx[(size_t)Sv * Bv * G4];

// h(t-1) pre-split bf16, WARP-BLOCKED layout (identical for all blocks):
//   region (bg = b>>4, kq = (k>>1)>>6) of 1024 words at (bg*4+kq)*1024;
//   within region: word = i*128 + lane*4 + (p&3), lane = g*4+t,
//   i = (row-half? 4:0) + (p>>2), p = fragment-order index in [0,16).
// Consumer: 8x LDG.128 per thread per array, each warp instr = 512B contig.
__device__ __align__(16) unsigned g_hhi_w[Bv * 256];
__device__ __align__(16) unsigned g_hlo_w[Bv * 256];

// Grid-barrier state (R13 counter/gen form — measured best).
__device__ unsigned int g_count = 0;
__device__ unsigned int g_gen   = 0;

#define NBLK 128

__device__ __forceinline__ unsigned cvt_tf32(float x) {
    unsigned u;
    asm("cvt.rna.tf32.f32 %0, %1;" : "=r"(u) : "f"(x));
    return u;
}

__device__ __forceinline__ void mma_tf32(float c[4], const unsigned a[4],
                                         const unsigned b[2]) {
    asm("mma.sync.aligned.m16n8k8.row.col.f32.tf32.tf32.f32 "
        "{%0,%1,%2,%3}, {%4,%5,%6,%7}, {%8,%9}, {%0,%1,%2,%3};"
        : "+f"(c[0]), "+f"(c[1]), "+f"(c[2]), "+f"(c[3])
        : "r"(a[0]), "r"(a[1]), "r"(a[2]), "r"(a[3]),
          "r"(b[0]), "r"(b[1]));
}

__device__ __forceinline__ void mma_bf16(float c[4], const unsigned a[4],
                                         const unsigned b[2]) {
    asm("mma.sync.aligned.m16n8k16.row.col.f32.bf16.bf16.f32 "
        "{%0,%1,%2,%3}, {%4,%5,%6,%7}, {%8,%9}, {%0,%1,%2,%3};"
        : "+f"(c[0]), "+f"(c[1]), "+f"(c[2]), "+f"(c[3])
        : "r"(a[0]), "r"(a[1]), "r"(a[2]), "r"(a[3]),
          "r"(b[0]), "r"(b[1]));
}

__device__ __forceinline__ void bf16_split2(float e0, float e1,
                                            unsigned& hi, unsigned& lo) {
    asm("cvt.rn.bf16x2.f32 %0, %1, %2;" : "=r"(hi) : "f"(e1), "f"(e0));
    float f0 = __uint_as_float(hi << 16);
    float f1 = __uint_as_float(hi & 0xffff0000u);
    float r0 = e0 - f0;
    float r1 = e1 - f1;
    asm("cvt.rn.bf16x2.f32 %0, %1, %2;" : "=r"(lo) : "f"(r1), "f"(r0));
}

__device__ __forceinline__ unsigned short bf16_of(float x) {
    unsigned short h;
    asm("cvt.rn.bf16.f32 %0, %1;" : "=h"(h) : "f"(x));
    return h;
}

// ===========================================================================
// Phase 1: gx = X[32768,512] @ W_ih^T[512,2048] + (b_ih + b_hh)
// tf32 mma.m16n8k8, 128x128 block tile, 8 warps, 64x32 warp tile. (R6, kept.)
// ===========================================================================
#define P1ROW 36

__global__ __launch_bounds__(256, 2) void gemm_x_tf32(
    const float* __restrict__ X,
    const float* __restrict__ W,
    const float* __restrict__ bih,
    const float* __restrict__ bhh)
{
    __shared__ unsigned As[128 * P1ROW];
    __shared__ unsigned Bs[128 * P1ROW];

    const int tid  = threadIdx.x;
    const int wid  = tid >> 5;
    const int lane = tid & 31;
    const int g    = lane >> 2;
    const int t    = lane & 3;

    const int m0 = blockIdx.y * 128;
    const int n0 = blockIdx.x * 128;
    const int wm = (wid >> 2) * 64;
    const int wn = (wid & 3) * 32;

    const int lr  = tid >> 3;
    const int lc4 = (tid & 7) * 4;

    float acc[4][4][4];
#pragma unroll
    for (int mi = 0; mi < 4; mi++)
#pragma unroll
        for (int nj = 0; nj < 4; nj++)
#pragma unroll
            for (int q = 0; q < 4; q++) acc[mi][nj][q] = 0.f;

    for (int k0 = 0; k0 < FINv; k0 += 32) {
#pragma unroll
        for (int rr = 0; rr < 128; rr += 32) {
            int row = lr + rr;
            float4 av = *reinterpret_cast<const float4*>(
                X + (size_t)(m0 + row) * FINv + k0 + lc4);
            uint4 at = make_uint4(cvt_tf32(av.x), cvt_tf32(av.y),
                                  cvt_tf32(av.z), cvt_tf32(av.w));
            *reinterpret_cast<uint4*>(&As[row * P1ROW + lc4]) = at;
            float4 bv = *reinterpret_cast<const float4*>(
                W + (size_t)(n0 + row) * FINv + k0 + lc4);
            uint4 bt = make_uint4(cvt_tf32(bv.x), cvt_tf32(bv.y),
                                  cvt_tf32(bv.z), cvt_tf32(bv.w));
            *reinterpret_cast<uint4*>(&Bs[row * P1ROW + lc4]) = bt;
        }
        __syncthreads();

#pragma unroll
        for (int kk = 0; kk < 32; kk += 8) {
            unsigned afr[4][4], bfr[4][2];
#pragma unroll
            for (int mi = 0; mi < 4; mi++) {
                int base = (wm + mi * 16 + g) * P1ROW + kk + t;
                afr[mi][0] = As[base];
                afr[mi][1] = As[base + 8 * P1ROW];
                afr[mi][2] = As[base + 4];
                afr[mi][3] = As[base + 8 * P1ROW + 4];
            }
#pragma unroll
            for (int nj = 0; nj < 4; nj++) {
                int bb = (wn + nj * 8 + g) * P1ROW + kk + t;
                bfr[nj][0] = Bs[bb];
                bfr[nj][1] = Bs[bb + 4];
            }
#pragma unroll
            for (int mi = 0; mi < 4; mi++)
#pragma unroll
                for (int nj = 0; nj < 4; nj++)
                    mma_tf32(acc[mi][nj], afr[mi], bfr[nj]);
        }
        __syncthreads();
    }

#pragma unroll
    for (int nj = 0; nj < 4; nj++) {
        int n = n0 + wn + nj * 8 + 2 * t;
        float bs0 = bih[n] + bhh[n];
        float bs1 = bih[n + 1] + bhh[n + 1];
#pragma unroll
        for (int mi = 0; mi < 4; mi++) {
            int row = m0 + wm + mi * 16 + g;
            float2 v0 = make_float2(acc[mi][nj][0] + bs0, acc[mi][nj][1] + bs1);
            float2 v1 = make_float2(acc[mi][nj][2] + bs0, acc[mi][nj][3] + bs1);
            *reinterpret_cast<float2*>(&g_gx[(size_t)row * G4 + n])       = v0;
            *reinterpret_cast<float2*>(&g_gx[(size_t)(row + 8) * G4 + n]) = v1;
        }
    }
}

// ===========================================================================
// Phase 2: persistent recurrence, bf16-pair tensor cores, 512 threads.
// A-fragments (h) load straight from the WARP-BLOCKED global arrays:
// 8x LDG.128 per thread per array, every warp transaction 512B contiguous.
// W (hi,lo) in smem; split-K=4 via 4-slab ex reduce; counter/gen barrier.
// ===========================================================================
#define HS 260
#define WHI_OFF 0
#define WLO_OFF (16 * HS)
#define EX_OFF  (32 * HS)                    // 8320
#define EXSLAB  (16 * 68)
#define SM2_WORDS (EX_OFF + 4 * EXSLAB)      // 12672 words = 50688 B

__global__ __launch_bounds__(512, 1) void lstm_rec_kernel(
    const float* __restrict__ whh,   // [2048][512]
    float* __restrict__ out)
{
    extern __shared__ unsigned smu[];
    unsigned* w_hi = smu + WHI_OFF;
    unsigned* w_lo = smu + WLO_OFF;
    float*    ex   = reinterpret_cast<float*>(smu + EX_OFF);  // [4][16][68]

    float* hs_out = out;
    float* cs_out = out + (size_t)Sv * Bv * Hv;

    const int tid  = threadIdx.x;
    const int wid  = tid >> 5;
    const int lane = tid & 31;
    const int g    = lane >> 2;
    const int t    = lane & 3;
    const int u0   = blockIdx.x * 4;
    const int kq   = wid >> 2;           // K quarter
    const int bb   = (wid & 3) * 16;     // batch base

    // W_hh split into packed bf16 (hi, lo) pair words, once.
    for (int i = tid; i < 16 * 256; i += 512) {
        int c = i >> 8, j = i & 255;
        int gr = ((c >> 2) * Hv) + u0 + (c & 3);
        float2 wv = *reinterpret_cast<const float2*>(whh + (size_t)gr * Hv + 2 * j);
        unsigned hi, lo;
        bf16_split2(wv.x, wv.y, hi, lo);
        w_hi[c * HS + j] = hi;
        w_lo[c * HS + j] = lo;
    }

    unsigned bar_base = 0;
    if (tid == 0) bar_base = atomicAdd(&g_gen, 0u);

    // A-fragment load base (word index): region (bg = wid&3, kq), lane slot.
    const int abase = (((wid & 3) * 4 + kq) << 10) + lane * 4;
    // B-fragment smem bases
    const int b0 = g * HS + t;
    const int b1 = (8 + g) * HS + t;
    const int jh = kq * 64;

    // Accumulator cols: nt*8 + 2t, +1 (adjacent units of the same gate)
    int gcol[2];
#pragma unroll
    for (int nt = 0; nt < 2; nt++) {
        int c = nt * 8 + 2 * t;
        gcol[nt] = ((c >> 2) * Hv) + u0 + (c & 3);
    }

    // Elementwise mapping (threads tid<256): one (unit,batch); c in register.
    const int u_e = tid & 3;
    const int b_e = (tid >> 2) & 63;
    // Producer-side warp-blocked h address (16-bit units) for (b_e, k=u0+u_e):
    int saddr;
    {
        int k   = u0 + u_e;
        int j   = k >> 1;
        int skq = j >> 6;
        int jl  = j & 63;
        int st  = jl & 3;
        int p   = ((jl >> 3) << 1) | ((jl >> 2) & 1);
        int sbg = b_e >> 4;
        int gp  = b_e & 15;
        int prt = gp >> 3;
        int sg  = gp & 7;
        int sl  = sg * 4 + st;
        int si  = prt * 4 + (p >> 2);
        int w   = ((sbg * 4 + skq) << 10) + si * 128 + sl * 4 + (p & 3);
        saddr   = (w << 1) | (k & 1);
    }
    float cpv = 0.f;

    __syncthreads();

    for (int t_s = 0; t_s < Sv; t_s++) {
        // ---- prefetch gx into regs ----
        float gxv[2][4];
        if (kq == 0) {
            const float* gxt = g_gx + (size_t)t_s * (Bv * G4);
#pragma unroll
            for (int nt = 0; nt < 2; nt++) {
                float2 lo = *reinterpret_cast<const float2*>(
                    gxt + (size_t)(bb + g) * G4 + gcol[nt]);
                float2 hi = *reinterpret_cast<const float2*>(
                    gxt + (size_t)(bb + g + 8) * G4 + gcol[nt]);
                gxv[nt][0] = lo.x; gxv[nt][1] = lo.y;
                gxv[nt][2] = hi.x; gxv[nt][3] = hi.y;
            }
        } else {
#pragma unroll
            for (int nt = 0; nt < 2; nt++)
#pragma unroll
                for (int q = 0; q < 4; q++) gxv[nt][q] = 0.f;
        }

        float acc[2][4];
#pragma unroll
        for (int nt = 0; nt < 2; nt++)
#pragma unroll
            for (int q = 0; q < 4; q++) acc[nt][q] = gxv[nt][q];

        if (t_s > 0) {
            // ---- grid barrier: all blocks finished step t_s-1 ----
            __syncthreads();
            if (tid == 0) {
                unsigned target = bar_base + (unsigned)t_s;
                if (atomicAdd(&g_count, 1u) == NBLK - 1u) {
                    atomicExch(&g_count, 0u);
                    __threadfence();
                    atomicExch(&g_gen, target);
                } else {
                    while ((int)(atomicAdd(&g_gen, 0u) - target) < 0) { }
                }
                __threadfence();
            }
            __syncthreads();

            // ---- load A-fragments: 8x LDG.128 per array, fully coalesced ----
            union { uint4 v[4]; unsigned u[16]; } r0h, r1h, r0l, r1l;
            {
                const uint4* ph = reinterpret_cast<const uint4*>(g_hhi_w + abase);
                const uint4* pl = reinterpret_cast<const uint4*>(g_hlo_w + abase);
#pragma unroll
                for (int i = 0; i < 4; i++) {
                    r0h.v[i] = __ldcg(ph + i * 32);
                    r1h.v[i] = __ldcg(ph + (i + 4) * 32);
                    r0l.v[i] = __ldcg(pl + i * 32);
                    r1l.v[i] = __ldcg(pl + (i + 4) * 32);
                }
            }

            // ---- bf16-pair recurrent GEMM: K quarter ----
#pragma unroll
            for (int kt = 0; kt < 8; kt++) {
                int jb = jh + kt * 8;
                unsigned ah[4], al[4], bh[2][2], bl[2][2];
                ah[0] = r0h.u[2 * kt];     ah[1] = r1h.u[2 * kt];
                ah[2] = r0h.u[2 * kt + 1]; ah[3] = r1h.u[2 * kt + 1];
                al[0] = r0l.u[2 * kt];     al[1] = r1l.u[2 * kt];
                al[2] = r0l.u[2 * kt + 1]; al[3] = r1l.u[2 * kt + 1];
                bh[0][0] = w_hi[b0 + jb];  bh[0][1] = w_hi[b0 + jb + 4];
                bh[1][0] = w_hi[b1 + jb];  bh[1][1] = w_hi[b1 + jb + 4];
                bl[0][0] = w_lo[b0 + jb];  bl[0][1] = w_lo[b0 + jb + 4];
                bl[1][0] = w_lo[b1 + jb];  bl[1][1] = w_lo[b1 + jb + 4];
#pragma unroll
                for (int nt = 0; nt < 2; nt++) {
                    mma_bf16(acc[nt], ah, bh[nt]);   // Whi*Hhi
                    mma_bf16(acc[nt], al, bh[nt]);   // Whi*Hlo
                    mma_bf16(acc[nt], ah, bl[nt]);   // Wlo*Hhi
                }
            }
        }

        // ---- write split-K partials to ex[kq] ----
        {
            float* exs = ex + kq * EXSLAB;
#pragma unroll
            for (int nt = 0; nt < 2; nt++) {
                int c = nt * 8 + 2 * t;
                exs[c * 68 + bb + g]           = acc[nt][0];
                exs[(c + 1) * 68 + bb + g]     = acc[nt][1];
                exs[c * 68 + bb + g + 8]       = acc[nt][2];
                exs[(c + 1) * 68 + bb + g + 8] = acc[nt][3];
            }
        }
        __syncthreads();

        // ---- fused 4-way reduce + LSTM update + warp-blocked h store ----
        if (tid < 256) {
            float gate[4];
#pragma unroll
            for (int gg4 = 0; gg4 < 4; gg4++) {
                int c = gg4 * 4 + u_e;
                float s = ex[c * 68 + b_e];
#pragma unroll
                for (int sk = 1; sk < 4; sk++)
                    s += ex[sk * EXSLAB + c * 68 + b_e];
                gate[gg4] = s;
            }
            float si = 1.f / (1.f + expf(-gate[0]));
            float sf = 1.f / (1.f + expf(-gate[1]));
            float tg = tanhf(gate[2]);
            float so = 1.f / (1.f + expf(-gate[3]));
            float cc = sf * cpv + si * tg;
            cpv = cc;
            float hh = so * tanhf(cc);
            // pre-split h for next step, warp-blocked layout
            unsigned short hi16 = bf16_of(hh);
            float fhi = __uint_as_float(((unsigned)hi16) << 16);
            unsigned short lo16 = bf16_of(hh - fhi);
            reinterpret_cast<unsigned short*>(g_hhi_w)[saddr] = hi16;
            reinterpret_cast<unsigned short*>(g_hlo_w)[saddr] = lo16;
            // fp32 outputs
            size_t o = (size_t)t_s * Bv * Hv + (size_t)b_e * Hv + u0 + u_e;
            __stcg(hs_out + o, hh);
            __stcg(cs_out + o, cc);
            __threadfence();   // make h stores visible before the arrive
        }
        // (next iteration's barrier __syncthreads orders the arrive)
    }
}

// ===========================================================================
// Launch
// ===========================================================================
extern "C" void kernel_launch(void* const* d_in, const int* in_sizes, int n_in,
                              void* d_out, int out_size)
{
    const float* seq  = (const float*)d_in[0];
    const float* w_ih = (const float*)d_in[1];
    const float* w_hh = (const float*)d_in[2];
    const float* b_ih = (const float*)d_in[3];
    const float* b_hh = (const float*)d_in[4];
    float* out = (float*)d_out;

    const int smem_p2 = SM2_WORDS * (int)sizeof(unsigned);   // 50688 B
    cudaFuncSetAttribute(lstm_rec_kernel,
                         cudaFuncAttributeMaxDynamicSharedMemorySize, smem_p2);

    dim3 g1(G4 / 128, (Sv * Bv) / 128);   // (16, 256)
    gemm_x_tf32<<<g1, 256>>>(seq, w_ih, b_ih, b_hh);
    lstm_rec_kernel<<<NBLK, 512, smem_p2>>>(w_hh, out);
}